// round 9
// baseline (speedup 1.0000x reference)
#include <cuda_runtime.h>

typedef unsigned long long u64;

// ---- packed f32x2 helpers (sm_103a) ----
__device__ __forceinline__ u64 fma2(u64 a, u64 b, u64 c) {
    u64 d;
    asm("fma.rn.f32x2 %0, %1, %2, %3;" : "=l"(d) : "l"(a), "l"(b), "l"(c));
    return d;
}
__device__ __forceinline__ u64 mul2(u64 a, u64 b) {
    u64 d;
    asm("mul.rn.f32x2 %0, %1, %2;" : "=l"(d) : "l"(a), "l"(b));
    return d;
}
__device__ __forceinline__ u64 add2(u64 a, u64 b) {
    u64 d;
    asm("add.rn.f32x2 %0, %1, %2;" : "=l"(d) : "l"(a), "l"(b));
    return d;
}
__device__ __forceinline__ u64 relu2(u64 v) {
    unsigned a, b;
    asm("mov.b64 {%0, %1}, %2;" : "=r"(a), "=r"(b) : "l"(v));
    float lo = fmaxf(__uint_as_float(a), 0.0f);
    float hi = fmaxf(__uint_as_float(b), 0.0f);
    u64 d;
    asm("mov.b64 %0, {%1, %2};" : "=l"(d) : "r"(__float_as_uint(lo)), "r"(__float_as_uint(hi)));
    return d;
}
__device__ __forceinline__ u64 lds64(unsigned a) {
    u64 v;
    asm volatile("ld.shared.b64 %0, [%1];" : "=l"(v) : "r"(a));
    return v;
}

// ---- problem constants ----
constexpr int W_DIM = 4096;
constexpr int C_DIM = 64;
constexpr int L_SEG = 512;              // outputs per warp
constexpr int SEGS  = W_DIM / L_SEG;    // 8
constexpr int BH    = 16 * 21;          // 336 rows
constexpr int WU_IT = 2;                // warmup iterations (64 steps)
constexpr int N_IT  = 18;               // total iterations (576 steps)
constexpr int DEPTH = 2;                // cp.async pipeline depth (blocks)
constexpr int BLK_BYTES = 32 * 256;     // 32 positions x 256 B = 8 KB
constexpr int WARP_SMEM = DEPTH * BLK_BYTES;          // 16 KB per warp
constexpr int SMEM_TOTAL = 2 * WARP_SMEM;             // 32 KB per 64-thr block

// Cross-correlation, zero pad. pad_lo: d=1 -> 3, d=2 -> 7, d=4 -> 14.
// y1[w] = relu(sum_k x [w- 3+  k] * w1[k])
// y2[w] = relu(sum_k y1[w- 7+ 2k] * w2[k])   (y1 := 0 outside [0,W))
// y3[w] = relu(sum_k y2[w-14+ 4k] * w3[k])   (y2 := 0 outside [0,W))
//
// R5 schedule (best): per warp, lane = 2 packed channels, t0 = s0-36.
// smem blk b holds positions t0+8+32b .. t0+39+32b (8 KB, gmem-contiguous).
// step i (iter k = i/32, u = i&31):
//   LDS    x pos t0+i+8 from blk k, offs u  -> xr[(u+8)&15]  (8-step lead)
//   STAGE1 y1 @ t0+i-4   -> y1r[u&15]     (x slots i-7..i)
//   STAGE2 y2 @ t0+i-12  -> y2r[u&31]     (y1 steps i-15..i-1, 1-step lag)
//   STAGE3 y3 @ t0+i-28  -> STG           (y2 steps i-30..i-2, 2-step lag)
// cp.async zero-fills OOB positions (src_size=0) -> no gmem branches.
// This round's single change vs R5: 64-thr blocks + launch_bounds(64,5)
// -> 10 warps/SM (was 8), reg budget 204 (carried state ~198), DEPTH 3->2
// to fit 5 blocks x 32 KB smem.

__device__ __forceinline__ void prefetch_blk(const char* gsrc, int p0,
                                             unsigned sdst, int lane)
{
    #pragma unroll
    for (int j = 0; j < 16; ++j) {
        const int idx = j * 32 + lane;           // 16B chunk index in the 8KB blk
        const int p   = p0 + (idx >> 4);         // position this chunk belongs to
        const unsigned ok = (p >= 0 && p < W_DIM) ? 16u : 0u;
        asm volatile("cp.async.cg.shared.global [%0], [%1], 16, %2;"
                     :: "r"(sdst + idx * 16), "l"(gsrc + idx * 16), "r"(ok)
                     : "memory");
    }
    asm volatile("cp.async.commit_group;" ::: "memory");
}

#define LDS_STEP(u)                                                            \
    {                                                                          \
        xr[((u) + 8) & 15] = lds64(cons + (u) * 256);                          \
    }

#define STAGE1(u)                                                              \
    {                                                                          \
        u64 a0 = mul2(xr[((u) - 7) & 15], w1r[0]);                             \
        u64 a1 = mul2(xr[((u) - 6) & 15], w1r[1]);                             \
        a0 = fma2(xr[((u) - 5) & 15], w1r[2], a0);                             \
        a1 = fma2(xr[((u) - 4) & 15], w1r[3], a1);                             \
        a0 = fma2(xr[((u) - 3) & 15], w1r[4], a0);                             \
        a1 = fma2(xr[((u) - 2) & 15], w1r[5], a1);                             \
        a0 = fma2(xr[((u) - 1) & 15], w1r[6], a0);                             \
        a1 = fma2(xr[((u) - 0) & 15], w1r[7], a1);                             \
        u64 y1v = relu2(add2(a0, a1));                                         \
        if (BOUNDARY) {                                                        \
            const int p1 = pb + (u) - 4;                                       \
            if (p1 < 0 || p1 >= W_DIM) y1v = 0ull;                             \
        }                                                                      \
        y1r[(u) & 15] = y1v;                                                   \
    }

#define STAGE2(u)                                                              \
    {                                                                          \
        u64 b0 = mul2(y1r[((u) - 15) & 15], w2r[0]);                           \
        u64 b1 = mul2(y1r[((u) - 13) & 15], w2r[1]);                           \
        b0 = fma2(y1r[((u) - 11) & 15], w2r[2], b0);                           \
        b1 = fma2(y1r[((u) -  9) & 15], w2r[3], b1);                           \
        b0 = fma2(y1r[((u) -  7) & 15], w2r[4], b0);                           \
        b1 = fma2(y1r[((u) -  5) & 15], w2r[5], b1);                           \
        b0 = fma2(y1r[((u) -  3) & 15], w2r[6], b0);                           \
        b1 = fma2(y1r[((u) -  1) & 15], w2r[7], b1);                           \
        u64 y2v = relu2(add2(b0, b1));                                         \
        if (BOUNDARY) {                                                        \
            const int p2 = pb + (u) - 12;                                      \
            if (p2 < 0 || p2 >= W_DIM) y2v = 0ull;                             \
        }                                                                      \
        y2r[(u) & 31] = y2v;                                                   \
    }

#define STAGE3_STORE(u)                                                        \
    {                                                                          \
        u64 c0 = mul2(y2r[((u) - 30) & 31], w3r[0]);                           \
        u64 c1 = mul2(y2r[((u) - 26) & 31], w3r[1]);                           \
        c0 = fma2(y2r[((u) - 22) & 31], w3r[2], c0);                           \
        c1 = fma2(y2r[((u) - 18) & 31], w3r[3], c1);                           \
        c0 = fma2(y2r[((u) - 14) & 31], w3r[4], c0);                           \
        c1 = fma2(y2r[((u) - 10) & 31], w3r[5], c1);                           \
        c0 = fma2(y2r[((u) -  6) & 31], w3r[6], c0);                           \
        c1 = fma2(y2r[((u) -  2) & 31], w3r[7], c1);                           \
        const u64 y3v = relu2(add2(c0, c1));                                   \
        __stcs((u64*)(sp + (u) * C_DIM), y3v);                                 \
    }

template<bool BOUNDARY>
__device__ __forceinline__ void run_seg(
    const float* __restrict__ x,
    const u64* w1r, const u64* w2r, const u64* w3r,
    float* __restrict__ out,
    int bh, int seg, int lane, unsigned wsm)
{
    const int s0 = seg * L_SEG;
    const int t0 = s0 - 36;

    // prefetch stream: blk b = positions t0+8+32b .. t0+39+32b (8KB contiguous)
    const char* gpf = (const char*)x
                    + ((long long)bh * W_DIM + (t0 + 8)) * (C_DIM * 4);
    int ppf = t0 + 8;

    #pragma unroll
    for (int b = 0; b < DEPTH; ++b) {
        prefetch_blk(gpf, ppf, wsm + b * BLK_BYTES, lane);
        gpf += BLK_BYTES;
        ppf += 32;
    }

    float* sp = out + ((long long)bh * W_DIM + s0) * C_DIM + 2 * lane;
    int pb = t0;                                 // position of step at u=0

    u64 xr[16], y1r[16], y2r[32];
    #pragma unroll
    for (int j = 0; j < 16; ++j) xr[j]  = 0ull;
    #pragma unroll
    for (int j = 0; j < 16; ++j) y1r[j] = 0ull;
    #pragma unroll
    for (int j = 0; j < 32; ++j) y2r[j] = 0ull;

    unsigned cons = wsm + 2 * lane * 4;          // slot 0 base + lane offset
    const unsigned cons_hi = wsm + DEPTH * BLK_BYTES;

    for (int k = 0; k < N_IT; ++k) {
        if (k == N_IT - 1) asm volatile("cp.async.wait_group 0;" ::: "memory");
        else               asm volatile("cp.async.wait_group 1;" ::: "memory");
        __syncwarp();

        if (k < WU_IT) {
            #pragma unroll
            for (int u = 0; u < 32; ++u) {
                LDS_STEP(u) STAGE1(u) STAGE2(u)
            }
        } else {
            #pragma unroll
            for (int u = 0; u < 32; ++u) {
                LDS_STEP(u) STAGE1(u) STAGE2(u) STAGE3_STORE(u)
            }
            sp += 32 * C_DIM;
        }

        // refill just-consumed slot with blk k+DEPTH
        if (k + DEPTH < N_IT) {
            prefetch_blk(gpf, ppf, cons - 2 * lane * 4, lane);
            gpf += BLK_BYTES;
            ppf += 32;
        }

        cons += BLK_BYTES;
        if (cons >= cons_hi) cons -= DEPTH * BLK_BYTES;
        pb += 32;
    }
}

__global__ void __launch_bounds__(64, 5)
conv_stack_kernel(const float* __restrict__ x,
                  const float* __restrict__ w1,
                  const float* __restrict__ w2,
                  const float* __restrict__ w3,
                  float* __restrict__ out)
{
    extern __shared__ char smem[];

    const int wib  = threadIdx.x >> 5;            // warp in block (0..1)
    const int warp = blockIdx.x * 2 + wib;
    const int lane = threadIdx.x & 31;

    const unsigned wsm = (unsigned)__cvta_generic_to_shared(smem + wib * WARP_SMEM);

    const int bh  = warp >> 3;        // warp / SEGS
    const int seg = warp & 7;         // warp % SEGS

    u64 w1r[8], w2r[8], w3r[8];
    #pragma unroll
    for (int k = 0; k < 8; ++k) {
        w1r[k] = *(const u64*)(w1 + k * C_DIM + 2 * lane);
        w2r[k] = *(const u64*)(w2 + k * C_DIM + 2 * lane);
        w3r[k] = *(const u64*)(w3 + k * C_DIM + 2 * lane);
    }

    if (seg == 0 || seg == SEGS - 1) {
        run_seg<true >(x, w1r, w2r, w3r, out, bh, seg, lane, wsm);
    } else {
        run_seg<false>(x, w1r, w2r, w3r, out, bh, seg, lane, wsm);
    }
}

extern "C" void kernel_launch(void* const* d_in, const int* in_sizes, int n_in,
                              void* d_out, int out_size)
{
    const float* x  = (const float*)d_in[0];
    const float* w1 = (const float*)d_in[1];
    const float* w2 = (const float*)d_in[2];
    const float* w3 = (const float*)d_in[3];
    float* out = (float*)d_out;

    (void)in_sizes; (void)n_in; (void)out_size;

    cudaFuncSetAttribute(conv_stack_kernel,
                         cudaFuncAttributeMaxDynamicSharedMemorySize, SMEM_TOTAL);

    // 336 rows * 8 segs = 2688 warps -> 1344 blocks of 64 threads
    conv_stack_kernel<<<(BH * SEGS) / 2, 64, SMEM_TOTAL>>>(x, w1, w2, w3, out);
}

// round 10
// speedup vs baseline: 1.2562x; 1.2562x over previous
#include <cuda_runtime.h>

typedef unsigned long long u64;

// ---- packed f32x2 helpers (sm_103a) ----
__device__ __forceinline__ u64 fma2(u64 a, u64 b, u64 c) {
    u64 d;
    asm("fma.rn.f32x2 %0, %1, %2, %3;" : "=l"(d) : "l"(a), "l"(b), "l"(c));
    return d;
}
__device__ __forceinline__ u64 mul2(u64 a, u64 b) {
    u64 d;
    asm("mul.rn.f32x2 %0, %1, %2;" : "=l"(d) : "l"(a), "l"(b));
    return d;
}
__device__ __forceinline__ u64 relu2(u64 v) {
    unsigned a, b;
    asm("mov.b64 {%0, %1}, %2;" : "=r"(a), "=r"(b) : "l"(v));
    float lo = fmaxf(__uint_as_float(a), 0.0f);
    float hi = fmaxf(__uint_as_float(b), 0.0f);
    u64 d;
    asm("mov.b64 %0, {%1, %2};" : "=l"(d) : "r"(__float_as_uint(lo)), "r"(__float_as_uint(hi)));
    return d;
}
__device__ __forceinline__ u64 lds64(unsigned a) {
    u64 v;
    asm volatile("ld.shared.b64 %0, [%1];" : "=l"(v) : "r"(a));
    return v;
}

// ---- problem constants ----
constexpr int W_DIM = 4096;
constexpr int C_DIM = 64;
constexpr int L_SEG = 512;              // outputs per warp
constexpr int SEGS  = W_DIM / L_SEG;    // 8
constexpr int BH    = 16 * 21;          // 336 rows
constexpr int WU_IT = 2;                // warmup iterations (64 steps)
constexpr int N_IT  = 18;               // total iterations (576 steps)
constexpr int DEPTH = 3;                // cp.async pipeline depth (blocks)
constexpr int BLK_BYTES = 32 * 256;     // 32 positions x 256 B = 8 KB
constexpr int WARP_SMEM = DEPTH * BLK_BYTES;          // 24 KB per warp
constexpr int SMEM_TOTAL = 3 * WARP_SMEM;             // 72 KB per 96-thr block

// Cross-correlation, zero pad. pad_lo: d=1 -> 3, d=2 -> 7, d=4 -> 14.
// y1[w] = relu(sum_k x [w- 3+  k] * w1[k])
// y2[w] = relu(sum_k y1[w- 7+ 2k] * w2[k])   (y1 := 0 outside [0,W))
// y3[w] = relu(sum_k y2[w-14+ 4k] * w3[k])   (y2 := 0 outside [0,W))
//
// R5 schedule (best known): per warp, lane = 2 packed channels, t0 = s0-36.
// smem blk b holds positions t0+8+32b .. t0+39+32b (8 KB, gmem-contiguous).
// step i (iter k = i/32, u = i&31):
//   LDS    x pos t0+i+8 from blk k, offs u  -> xr[(u+8)&15]  (8-step lead)
//   STAGE1 y1 @ t0+i-4   -> y1r[u&15]     (x slots i-7..i)
//   STAGE2 y2 @ t0+i-12  -> y2r[u&31]     (y1 steps i-15..i-1, 1-step lag)
//   STAGE3 y3 @ t0+i-28  -> STG           (y2 steps i-30..i-2, 2-step lag)
// cp.async zero-fills OOB positions (src_size=0) -> no gmem branches.
// R10 changes: 96-thr blocks + launch_bounds(96,3) -> 9 warps/SM, 227-reg
// budget (above the ~206 needed: no spill, unlike the 204-budget R9 which
// collapsed); single-chain 8-deep fma accumulation (24 fma-pipe ops/step
// instead of 27, fewer live temps).

__device__ __forceinline__ void prefetch_blk(const char* gsrc, int p0,
                                             unsigned sdst, int lane)
{
    #pragma unroll
    for (int j = 0; j < 16; ++j) {
        const int idx = j * 32 + lane;           // 16B chunk index in the 8KB blk
        const int p   = p0 + (idx >> 4);         // position this chunk belongs to
        const unsigned ok = (p >= 0 && p < W_DIM) ? 16u : 0u;
        asm volatile("cp.async.cg.shared.global [%0], [%1], 16, %2;"
                     :: "r"(sdst + idx * 16), "l"(gsrc + idx * 16), "r"(ok)
                     : "memory");
    }
    asm volatile("cp.async.commit_group;" ::: "memory");
}

#define LDS_STEP(u)                                                            \
    {                                                                          \
        xr[((u) + 8) & 15] = lds64(cons + (u) * 256);                          \
    }

#define STAGE1(u)                                                              \
    {                                                                          \
        u64 a0 = mul2(xr[((u) - 7) & 15], w1r[0]);                             \
        a0 = fma2(xr[((u) - 6) & 15], w1r[1], a0);                             \
        a0 = fma2(xr[((u) - 5) & 15], w1r[2], a0);                             \
        a0 = fma2(xr[((u) - 4) & 15], w1r[3], a0);                             \
        a0 = fma2(xr[((u) - 3) & 15], w1r[4], a0);                             \
        a0 = fma2(xr[((u) - 2) & 15], w1r[5], a0);                             \
        a0 = fma2(xr[((u) - 1) & 15], w1r[6], a0);                             \
        a0 = fma2(xr[((u) - 0) & 15], w1r[7], a0);                             \
        u64 y1v = relu2(a0);                                                   \
        if (BOUNDARY) {                                                        \
            const int p1 = pb + (u) - 4;                                       \
            if (p1 < 0 || p1 >= W_DIM) y1v = 0ull;                             \
        }                                                                      \
        y1r[(u) & 15] = y1v;                                                   \
    }

#define STAGE2(u)                                                              \
    {                                                                          \
        u64 b0 = mul2(y1r[((u) - 15) & 15], w2r[0]);                           \
        b0 = fma2(y1r[((u) - 13) & 15], w2r[1], b0);                           \
        b0 = fma2(y1r[((u) - 11) & 15], w2r[2], b0);                           \
        b0 = fma2(y1r[((u) -  9) & 15], w2r[3], b0);                           \
        b0 = fma2(y1r[((u) -  7) & 15], w2r[4], b0);                           \
        b0 = fma2(y1r[((u) -  5) & 15], w2r[5], b0);                           \
        b0 = fma2(y1r[((u) -  3) & 15], w2r[6], b0);                           \
        b0 = fma2(y1r[((u) -  1) & 15], w2r[7], b0);                           \
        u64 y2v = relu2(b0);                                                   \
        if (BOUNDARY) {                                                        \
            const int p2 = pb + (u) - 12;                                      \
            if (p2 < 0 || p2 >= W_DIM) y2v = 0ull;                             \
        }                                                                      \
        y2r[(u) & 31] = y2v;                                                   \
    }

#define STAGE3_STORE(u)                                                        \
    {                                                                          \
        u64 c0 = mul2(y2r[((u) - 30) & 31], w3r[0]);                           \
        c0 = fma2(y2r[((u) - 26) & 31], w3r[1], c0);                           \
        c0 = fma2(y2r[((u) - 22) & 31], w3r[2], c0);                           \
        c0 = fma2(y2r[((u) - 18) & 31], w3r[3], c0);                           \
        c0 = fma2(y2r[((u) - 14) & 31], w3r[4], c0);                           \
        c0 = fma2(y2r[((u) - 10) & 31], w3r[5], c0);                           \
        c0 = fma2(y2r[((u) -  6) & 31], w3r[6], c0);                           \
        c0 = fma2(y2r[((u) -  2) & 31], w3r[7], c0);                           \
        const u64 y3v = relu2(c0);                                             \
        __stcs((u64*)(sp + (u) * C_DIM), y3v);                                 \
    }

template<bool BOUNDARY>
__device__ __forceinline__ void run_seg(
    const float* __restrict__ x,
    const u64* w1r, const u64* w2r, const u64* w3r,
    float* __restrict__ out,
    int bh, int seg, int lane, unsigned wsm)
{
    const int s0 = seg * L_SEG;
    const int t0 = s0 - 36;

    // prefetch stream: blk b = positions t0+8+32b .. t0+39+32b (8KB contiguous)
    const char* gpf = (const char*)x
                    + ((long long)bh * W_DIM + (t0 + 8)) * (C_DIM * 4);
    int ppf = t0 + 8;

    #pragma unroll
    for (int b = 0; b < DEPTH; ++b) {
        prefetch_blk(gpf, ppf, wsm + b * BLK_BYTES, lane);
        gpf += BLK_BYTES;
        ppf += 32;
    }

    float* sp = out + ((long long)bh * W_DIM + s0) * C_DIM + 2 * lane;
    int pb = t0;                                 // position of step at u=0

    u64 xr[16], y1r[16], y2r[32];
    #pragma unroll
    for (int j = 0; j < 16; ++j) xr[j]  = 0ull;
    #pragma unroll
    for (int j = 0; j < 16; ++j) y1r[j] = 0ull;
    #pragma unroll
    for (int j = 0; j < 32; ++j) y2r[j] = 0ull;

    unsigned cons = wsm + 2 * lane * 4;          // slot 0 base + lane offset
    const unsigned cons_hi = wsm + DEPTH * BLK_BYTES;

    for (int k = 0; k < N_IT; ++k) {
        if (k == N_IT - 1) asm volatile("cp.async.wait_group 0;" ::: "memory");
        else               asm volatile("cp.async.wait_group 1;" ::: "memory");
        __syncwarp();

        if (k < WU_IT) {
            #pragma unroll
            for (int u = 0; u < 32; ++u) {
                LDS_STEP(u) STAGE1(u) STAGE2(u)
            }
        } else {
            #pragma unroll
            for (int u = 0; u < 32; ++u) {
                LDS_STEP(u) STAGE1(u) STAGE2(u) STAGE3_STORE(u)
            }
            sp += 32 * C_DIM;
        }

        // refill just-consumed slot with blk k+DEPTH
        if (k + DEPTH < N_IT) {
            prefetch_blk(gpf, ppf, cons - 2 * lane * 4, lane);
            gpf += BLK_BYTES;
            ppf += 32;
        }

        cons += BLK_BYTES;
        if (cons >= cons_hi) cons -= DEPTH * BLK_BYTES;
        pb += 32;
    }
}

__global__ void __launch_bounds__(96, 3)
conv_stack_kernel(const float* __restrict__ x,
                  const float* __restrict__ w1,
                  const float* __restrict__ w2,
                  const float* __restrict__ w3,
                  float* __restrict__ out)
{
    extern __shared__ char smem[];

    const int wib  = threadIdx.x >> 5;            // warp in block (0..2)
    const int warp = blockIdx.x * 3 + wib;
    const int lane = threadIdx.x & 31;

    const unsigned wsm = (unsigned)__cvta_generic_to_shared(smem + wib * WARP_SMEM);

    const int bh  = warp >> 3;        // warp / SEGS
    const int seg = warp & 7;         // warp % SEGS

    u64 w1r[8], w2r[8], w3r[8];
    #pragma unroll
    for (int k = 0; k < 8; ++k) {
        w1r[k] = *(const u64*)(w1 + k * C_DIM + 2 * lane);
        w2r[k] = *(const u64*)(w2 + k * C_DIM + 2 * lane);
        w3r[k] = *(const u64*)(w3 + k * C_DIM + 2 * lane);
    }

    if (seg == 0 || seg == SEGS - 1) {
        run_seg<true >(x, w1r, w2r, w3r, out, bh, seg, lane, wsm);
    } else {
        run_seg<false>(x, w1r, w2r, w3r, out, bh, seg, lane, wsm);
    }
}

extern "C" void kernel_launch(void* const* d_in, const int* in_sizes, int n_in,
                              void* d_out, int out_size)
{
    const float* x  = (const float*)d_in[0];
    const float* w1 = (const float*)d_in[1];
    const float* w2 = (const float*)d_in[2];
    const float* w3 = (const float*)d_in[3];
    float* out = (float*)d_out;

    (void)in_sizes; (void)n_in; (void)out_size;

    cudaFuncSetAttribute(conv_stack_kernel,
                         cudaFuncAttributeMaxDynamicSharedMemorySize, SMEM_TOTAL);

    // 336 rows * 8 segs = 2688 warps -> 896 blocks of 96 threads
    conv_stack_kernel<<<(BH * SEGS) / 3, 96, SMEM_TOTAL>>>(x, w1, w2, w3, out);
}

// round 11
// speedup vs baseline: 1.6442x; 1.3089x over previous
#include <cuda_runtime.h>

typedef unsigned long long u64;

// ---- packed f32x2 helpers (sm_103a) ----
__device__ __forceinline__ u64 fma2(u64 a, u64 b, u64 c) {
    u64 d;
    asm("fma.rn.f32x2 %0, %1, %2, %3;" : "=l"(d) : "l"(a), "l"(b), "l"(c));
    return d;
}
__device__ __forceinline__ u64 mul2(u64 a, u64 b) {
    u64 d;
    asm("mul.rn.f32x2 %0, %1, %2;" : "=l"(d) : "l"(a), "l"(b));
    return d;
}
__device__ __forceinline__ u64 add2(u64 a, u64 b) {
    u64 d;
    asm("add.rn.f32x2 %0, %1, %2;" : "=l"(d) : "l"(a), "l"(b));
    return d;
}
__device__ __forceinline__ u64 relu2(u64 v) {
    unsigned a, b;
    asm("mov.b64 {%0, %1}, %2;" : "=r"(a), "=r"(b) : "l"(v));
    float lo = fmaxf(__uint_as_float(a), 0.0f);
    float hi = fmaxf(__uint_as_float(b), 0.0f);
    u64 d;
    asm("mov.b64 %0, {%1, %2};" : "=l"(d) : "r"(__float_as_uint(lo)), "r"(__float_as_uint(hi)));
    return d;
}
__device__ __forceinline__ u64 lds64(unsigned a) {
    u64 v;
    asm volatile("ld.shared.b64 %0, [%1];" : "=l"(v) : "r"(a));
    return v;
}

// ---- problem constants ----
constexpr int W_DIM = 4096;
constexpr int C_DIM = 64;
constexpr int L_SEG = 512;              // outputs per warp
constexpr int SEGS  = W_DIM / L_SEG;    // 8
constexpr int BH    = 16 * 21;          // 336 rows
constexpr int WU_IT = 2;                // warmup iterations (64 steps)
constexpr int N_IT  = 18;               // total iterations (576 steps)
constexpr int DEPTH = 3;                // cp.async pipeline depth (blocks)
constexpr int BLK_BYTES = 32 * 256;     // 32 positions x 256 B = 8 KB
constexpr int WARP_SMEM = DEPTH * BLK_BYTES;          // 24 KB per warp
constexpr int SMEM_TOTAL = 4 * WARP_SMEM;             // 96 KB per 128-thr block

// Cross-correlation, zero pad. pad_lo: d=1 -> 3, d=2 -> 7, d=4 -> 14.
// y1[w] = relu(sum_k x [w- 3+  k] * w1[k])
// y2[w] = relu(sum_k y1[w- 7+ 2k] * w2[k])   (y1 := 0 outside [0,W))
// y3[w] = relu(sum_k y2[w-14+ 4k] * w3[k])   (y2 := 0 outside [0,W))
//
// R5 schedule (proven best, 184 us): per warp, lane = 2 packed channels,
// t0 = s0-36. smem blk b holds positions t0+8+32b .. t0+39+32b (8 KB).
// step i (iter k = i/32, u = i&31):
//   LDS    x pos t0+i+8 from blk k, offs u  -> xr[(u+8)&15]  (8-step lead)
//   STAGE1 y1 @ t0+i-4   -> y1r[u&15]     (x slots i-7..i)
//   STAGE2 y2 @ t0+i-12  -> y2r[u&31]     (y1 steps i-15..i-1, 1-step lag)
//   STAGE3 y3 @ t0+i-28  -> STG           (y2 steps i-30..i-2, 2-step lag)
// cp.async zero-fills OOB positions (src_size=0) -> no gmem branches.
//
// R11 single change vs R5: cp.async wait depth corrected. At start of iter k
// the warp has committed k+3 groups (blks 0..k+2) and only needs blk k done,
// so wait_group 2 suffices. R5's wait_group 1 additionally stalled on blk
// k+1's DRAM round trip EVERY iteration. Tail iters need 1 then 0.
// MUST stay at 255-reg budget (128thr x 2 blocks): any lower launch_bounds
// makes ptxas demote y2r[32] to local memory (R6-R10 all collapsed to
// regs=168 with local traffic).

__device__ __forceinline__ void prefetch_blk(const char* gsrc, int p0,
                                             unsigned sdst, int lane)
{
    #pragma unroll
    for (int j = 0; j < 16; ++j) {
        const int idx = j * 32 + lane;           // 16B chunk index in the 8KB blk
        const int p   = p0 + (idx >> 4);         // position this chunk belongs to
        const unsigned ok = (p >= 0 && p < W_DIM) ? 16u : 0u;
        asm volatile("cp.async.cg.shared.global [%0], [%1], 16, %2;"
                     :: "r"(sdst + idx * 16), "l"(gsrc + idx * 16), "r"(ok)
                     : "memory");
    }
    asm volatile("cp.async.commit_group;" ::: "memory");
}

#define LDS_STEP(u)                                                            \
    {                                                                          \
        xr[((u) + 8) & 15] = lds64(cons + (u) * 256);                          \
    }

#define STAGE1(u)                                                              \
    {                                                                          \
        u64 a0 = mul2(xr[((u) - 7) & 15], w1r[0]);                             \
        u64 a1 = mul2(xr[((u) - 6) & 15], w1r[1]);                             \
        a0 = fma2(xr[((u) - 5) & 15], w1r[2], a0);                             \
        a1 = fma2(xr[((u) - 4) & 15], w1r[3], a1);                             \
        a0 = fma2(xr[((u) - 3) & 15], w1r[4], a0);                             \
        a1 = fma2(xr[((u) - 2) & 15], w1r[5], a1);                             \
        a0 = fma2(xr[((u) - 1) & 15], w1r[6], a0);                             \
        a1 = fma2(xr[((u) - 0) & 15], w1r[7], a1);                             \
        u64 y1v = relu2(add2(a0, a1));                                         \
        if (BOUNDARY) {                                                        \
            const int p1 = pb + (u) - 4;                                       \
            if (p1 < 0 || p1 >= W_DIM) y1v = 0ull;                             \
        }                                                                      \
        y1r[(u) & 15] = y1v;                                                   \
    }

#define STAGE2(u)                                                              \
    {                                                                          \
        u64 b0 = mul2(y1r[((u) - 15) & 15], w2r[0]);                           \
        u64 b1 = mul2(y1r[((u) - 13) & 15], w2r[1]);                           \
        b0 = fma2(y1r[((u) - 11) & 15], w2r[2], b0);                           \
        b1 = fma2(y1r[((u) -  9) & 15], w2r[3], b1);                           \
        b0 = fma2(y1r[((u) -  7) & 15], w2r[4], b0);                           \
        b1 = fma2(y1r[((u) -  5) & 15], w2r[5], b1);                           \
        b0 = fma2(y1r[((u) -  3) & 15], w2r[6], b0);                           \
        b1 = fma2(y1r[((u) -  1) & 15], w2r[7], b1);                           \
        u64 y2v = relu2(add2(b0, b1));                                         \
        if (BOUNDARY) {                                                        \
            const int p2 = pb + (u) - 12;                                      \
            if (p2 < 0 || p2 >= W_DIM) y2v = 0ull;                             \
        }                                                                      \
        y2r[(u) & 31] = y2v;                                                   \
    }

#define STAGE3_STORE(u)                                                        \
    {                                                                          \
        u64 c0 = mul2(y2r[((u) - 30) & 31], w3r[0]);                           \
        u64 c1 = mul2(y2r[((u) - 26) & 31], w3r[1]);                           \
        c0 = fma2(y2r[((u) - 22) & 31], w3r[2], c0);                           \
        c1 = fma2(y2r[((u) - 18) & 31], w3r[3], c1);                           \
        c0 = fma2(y2r[((u) - 14) & 31], w3r[4], c0);                           \
        c1 = fma2(y2r[((u) - 10) & 31], w3r[5], c1);                           \
        c0 = fma2(y2r[((u) -  6) & 31], w3r[6], c0);                           \
        c1 = fma2(y2r[((u) -  2) & 31], w3r[7], c1);                           \
        const u64 y3v = relu2(add2(c0, c1));                                   \
        __stcs((u64*)(sp + (u) * C_DIM), y3v);                                 \
    }

template<bool BOUNDARY>
__device__ __forceinline__ void run_seg(
    const float* __restrict__ x,
    const u64* w1r, const u64* w2r, const u64* w3r,
    float* __restrict__ out,
    int bh, int seg, int lane, unsigned wsm)
{
    const int s0 = seg * L_SEG;
    const int t0 = s0 - 36;

    // prefetch stream: blk b = positions t0+8+32b .. t0+39+32b (8KB contiguous)
    const char* gpf = (const char*)x
                    + ((long long)bh * W_DIM + (t0 + 8)) * (C_DIM * 4);
    int ppf = t0 + 8;

    #pragma unroll
    for (int b = 0; b < DEPTH; ++b) {
        prefetch_blk(gpf, ppf, wsm + b * BLK_BYTES, lane);
        gpf += BLK_BYTES;
        ppf += 32;
    }

    float* sp = out + ((long long)bh * W_DIM + s0) * C_DIM + 2 * lane;
    int pb = t0;                                 // position of step at u=0

    u64 xr[16], y1r[16], y2r[32];
    #pragma unroll
    for (int j = 0; j < 16; ++j) xr[j]  = 0ull;
    #pragma unroll
    for (int j = 0; j < 16; ++j) y1r[j] = 0ull;
    #pragma unroll
    for (int j = 0; j < 32; ++j) y2r[j] = 0ull;

    unsigned cons = wsm + 2 * lane * 4;          // slot 0 base + lane offset
    const unsigned cons_hi = wsm + DEPTH * BLK_BYTES;

    for (int k = 0; k < N_IT; ++k) {
        // Need only blk k complete here. Committed groups so far: k+DEPTH
        // (or capped at N_IT near the tail), so allowed outstanding =
        // committed - (k+1). Steady state with DEPTH=3: wait_group 2.
        if      (k >= N_IT - 1) asm volatile("cp.async.wait_group 0;" ::: "memory");
        else if (k == N_IT - 2) asm volatile("cp.async.wait_group 1;" ::: "memory");
        else                    asm volatile("cp.async.wait_group 2;" ::: "memory");
        __syncwarp();

        if (k < WU_IT) {
            #pragma unroll
            for (int u = 0; u < 32; ++u) {
                LDS_STEP(u) STAGE1(u) STAGE2(u)
            }
        } else {
            #pragma unroll
            for (int u = 0; u < 32; ++u) {
                LDS_STEP(u) STAGE1(u) STAGE2(u) STAGE3_STORE(u)
            }
            sp += 32 * C_DIM;
        }

        // refill just-consumed slot with blk k+DEPTH
        if (k + DEPTH < N_IT) {
            prefetch_blk(gpf, ppf, cons - 2 * lane * 4, lane);
            gpf += BLK_BYTES;
            ppf += 32;
        }

        cons += BLK_BYTES;
        if (cons >= cons_hi) cons -= DEPTH * BLK_BYTES;
        pb += 32;
    }
}

__global__ void __launch_bounds__(128)
conv_stack_kernel(const float* __restrict__ x,
                  const float* __restrict__ w1,
                  const float* __restrict__ w2,
                  const float* __restrict__ w3,
                  float* __restrict__ out)
{
    extern __shared__ char smem[];

    const int warp = blockIdx.x * 4 + (threadIdx.x >> 5);
    const int lane = threadIdx.x & 31;

    const unsigned wsm = (unsigned)__cvta_generic_to_shared(
        smem + (threadIdx.x >> 5) * WARP_SMEM);

    const int bh  = warp >> 3;        // warp / SEGS
    const int seg = warp & 7;         // warp % SEGS

    u64 w1r[8], w2r[8], w3r[8];
    #pragma unroll
    for (int k = 0; k < 8; ++k) {
        w1r[k] = *(const u64*)(w1 + k * C_DIM + 2 * lane);
        w2r[k] = *(const u64*)(w2 + k * C_DIM + 2 * lane);
        w3r[k] = *(const u64*)(w3 + k * C_DIM + 2 * lane);
    }

    if (seg == 0 || seg == SEGS - 1) {
        run_seg<true >(x, w1r, w2r, w3r, out, bh, seg, lane, wsm);
    } else {
        run_seg<false>(x, w1r, w2r, w3r, out, bh, seg, lane, wsm);
    }
}

extern "C" void kernel_launch(void* const* d_in, const int* in_sizes, int n_in,
                              void* d_out, int out_size)
{
    const float* x  = (const float*)d_in[0];
    const float* w1 = (const float*)d_in[1];
    const float* w2 = (const float*)d_in[2];
    const float* w3 = (const float*)d_in[3];
    float* out = (float*)d_out;

    (void)in_sizes; (void)n_in; (void)out_size;

    cudaFuncSetAttribute(conv_stack_kernel,
                         cudaFuncAttributeMaxDynamicSharedMemorySize, SMEM_TOTAL);

    // 336 rows * 8 segs = 2688 warps -> 672 blocks of 128 threads
    conv_stack_kernel<<<(BH * SEGS) / 4, 128, SMEM_TOTAL>>>(x, w1, w2, w3, out);
}

// round 12
// speedup vs baseline: 1.8462x; 1.1228x over previous
#include <cuda_runtime.h>

typedef unsigned long long u64;

// ---- packed f32x2 helpers (sm_103a) ----
__device__ __forceinline__ u64 fma2(u64 a, u64 b, u64 c) {
    u64 d;
    asm("fma.rn.f32x2 %0, %1, %2, %3;" : "=l"(d) : "l"(a), "l"(b), "l"(c));
    return d;
}
__device__ __forceinline__ u64 mul2(u64 a, u64 b) {
    u64 d;
    asm("mul.rn.f32x2 %0, %1, %2;" : "=l"(d) : "l"(a), "l"(b));
    return d;
}
__device__ __forceinline__ u64 add2(u64 a, u64 b) {
    u64 d;
    asm("add.rn.f32x2 %0, %1, %2;" : "=l"(d) : "l"(a), "l"(b));
    return d;
}
__device__ __forceinline__ u64 relu2(u64 v) {
    unsigned a, b;
    asm("mov.b64 {%0, %1}, %2;" : "=r"(a), "=r"(b) : "l"(v));
    float lo = fmaxf(__uint_as_float(a), 0.0f);
    float hi = fmaxf(__uint_as_float(b), 0.0f);
    u64 d;
    asm("mov.b64 %0, {%1, %2};" : "=l"(d) : "r"(__float_as_uint(lo)), "r"(__float_as_uint(hi)));
    return d;
}
__device__ __forceinline__ u64 lds64(unsigned a) {
    u64 v;
    asm volatile("ld.shared.b64 %0, [%1];" : "=l"(v) : "r"(a));
    return v;
}

// ---- problem constants ----
constexpr int W_DIM = 4096;
constexpr int C_DIM = 64;
constexpr int L_SEG = 256;              // outputs per warp (smaller item for balance)
constexpr int SEGS  = W_DIM / L_SEG;    // 16
constexpr int BH    = 16 * 21;          // 336 rows
constexpr int WU_IT = 2;                // warmup iterations (64 steps)
constexpr int N_IT  = (64 + L_SEG) / 32;              // 10 iterations
constexpr int DEPTH = 3;                // cp.async pipeline depth (blocks)
constexpr int BLK_BYTES = 32 * 256;     // 32 positions x 256 B = 8 KB
constexpr int WARP_SMEM = DEPTH * BLK_BYTES;          // 24 KB per 1-warp block

// Cross-correlation, zero pad. pad_lo: d=1 -> 3, d=2 -> 7, d=4 -> 14.
// y1[w] = relu(sum_k x [w- 3+  k] * w1[k])
// y2[w] = relu(sum_k y1[w- 7+ 2k] * w2[k])   (y1 := 0 outside [0,W))
// y3[w] = relu(sum_k y2[w-14+ 4k] * w3[k])   (y2 := 0 outside [0,W))
//
// R5/R11 schedule (proven): per warp, lane = 2 packed channels, t0 = s0-36.
// smem blk b holds positions t0+8+32b .. t0+39+32b (8 KB, gmem-contiguous).
// step i (iter k = i/32, u = i&31):
//   LDS    x pos t0+i+8 from blk k, offs u  -> xr[(u+8)&15]  (8-step lead)
//   STAGE1 y1 @ t0+i-4   -> y1r[u&15]     (x slots i-7..i)
//   STAGE2 y2 @ t0+i-12  -> y2r[u&31]     (y1 steps i-15..i-1, 1-step lag)
//   STAGE3 y3 @ t0+i-28  -> STG           (y2 steps i-30..i-2, 2-step lag)
// cp.async zero-fills OOB positions (src_size=0) -> no gmem branches.
//
// R12 changes vs R11 (inner loop untouched; MUST stay at 255-reg budget,
// lower budgets spill the y2 ring -> R6-R10 collapses):
//  * 1-warp blocks (32 thr): 8 blocks/SM = same 8 warps, but the scheduler
//    backfills warp-slots individually -> kills 4-warp-granularity tail.
//  * L_SEG 512 -> 256: item = 320 steps, max SMSP depth 1600 vs 1728 steps.
//  * iter 0 runs LDS+STAGE1 only: y2 of steps 0..31 is never read by any
//    stage-3 tap (earliest needed y2 step is 34), so skip 16 fma2 x 32 steps.

__device__ __forceinline__ void prefetch_blk(const char* gsrc, int p0,
                                             unsigned sdst, int lane)
{
    #pragma unroll
    for (int j = 0; j < 16; ++j) {
        const int idx = j * 32 + lane;           // 16B chunk index in the 8KB blk
        const int p   = p0 + (idx >> 4);         // position this chunk belongs to
        const unsigned ok = (p >= 0 && p < W_DIM) ? 16u : 0u;
        asm volatile("cp.async.cg.shared.global [%0], [%1], 16, %2;"
                     :: "r"(sdst + idx * 16), "l"(gsrc + idx * 16), "r"(ok)
                     : "memory");
    }
    asm volatile("cp.async.commit_group;" ::: "memory");
}

#define LDS_STEP(u)                                                            \
    {                                                                          \
        xr[((u) + 8) & 15] = lds64(cons + (u) * 256);                          \
    }

#define STAGE1(u)                                                              \
    {                                                                          \
        u64 a0 = mul2(xr[((u) - 7) & 15], w1r[0]);                             \
        u64 a1 = mul2(xr[((u) - 6) & 15], w1r[1]);                             \
        a0 = fma2(xr[((u) - 5) & 15], w1r[2], a0);                             \
        a1 = fma2(xr[((u) - 4) & 15], w1r[3], a1);                             \
        a0 = fma2(xr[((u) - 3) & 15], w1r[4], a0);                             \
        a1 = fma2(xr[((u) - 2) & 15], w1r[5], a1);                             \
        a0 = fma2(xr[((u) - 1) & 15], w1r[6], a0);                             \
        a1 = fma2(xr[((u) - 0) & 15], w1r[7], a1);                             \
        u64 y1v = relu2(add2(a0, a1));                                         \
        if (BOUNDARY) {                                                        \
            const int p1 = pb + (u) - 4;                                       \
            if (p1 < 0 || p1 >= W_DIM) y1v = 0ull;                             \
        }                                                                      \
        y1r[(u) & 15] = y1v;                                                   \
    }

#define STAGE2(u)                                                              \
    {                                                                          \
        u64 b0 = mul2(y1r[((u) - 15) & 15], w2r[0]);                           \
        u64 b1 = mul2(y1r[((u) - 13) & 15], w2r[1]);                           \
        b0 = fma2(y1r[((u) - 11) & 15], w2r[2], b0);                           \
        b1 = fma2(y1r[((u) -  9) & 15], w2r[3], b1);                           \
        b0 = fma2(y1r[((u) -  7) & 15], w2r[4], b0);                           \
        b1 = fma2(y1r[((u) -  5) & 15], w2r[5], b1);                           \
        b0 = fma2(y1r[((u) -  3) & 15], w2r[6], b0);                           \
        b1 = fma2(y1r[((u) -  1) & 15], w2r[7], b1);                           \
        u64 y2v = relu2(add2(b0, b1));                                         \
        if (BOUNDARY) {                                                        \
            const int p2 = pb + (u) - 12;                                      \
            if (p2 < 0 || p2 >= W_DIM) y2v = 0ull;                             \
        }                                                                      \
        y2r[(u) & 31] = y2v;                                                   \
    }

#define STAGE3_STORE(u)                                                        \
    {                                                                          \
        u64 c0 = mul2(y2r[((u) - 30) & 31], w3r[0]);                           \
        u64 c1 = mul2(y2r[((u) - 26) & 31], w3r[1]);                           \
        c0 = fma2(y2r[((u) - 22) & 31], w3r[2], c0);                           \
        c1 = fma2(y2r[((u) - 18) & 31], w3r[3], c1);                           \
        c0 = fma2(y2r[((u) - 14) & 31], w3r[4], c0);                           \
        c1 = fma2(y2r[((u) - 10) & 31], w3r[5], c1);                           \
        c0 = fma2(y2r[((u) -  6) & 31], w3r[6], c0);                           \
        c1 = fma2(y2r[((u) -  2) & 31], w3r[7], c1);                           \
        const u64 y3v = relu2(add2(c0, c1));                                   \
        __stcs((u64*)(sp + (u) * C_DIM), y3v);                                 \
    }

template<bool BOUNDARY>
__device__ __forceinline__ void run_seg(
    const float* __restrict__ x,
    const u64* w1r, const u64* w2r, const u64* w3r,
    float* __restrict__ out,
    int bh, int seg, int lane, unsigned wsm)
{
    const int s0 = seg * L_SEG;
    const int t0 = s0 - 36;

    // prefetch stream: blk b = positions t0+8+32b .. t0+39+32b (8KB contiguous)
    const char* gpf = (const char*)x
                    + ((long long)bh * W_DIM + (t0 + 8)) * (C_DIM * 4);
    int ppf = t0 + 8;

    #pragma unroll
    for (int b = 0; b < DEPTH; ++b) {
        prefetch_blk(gpf, ppf, wsm + b * BLK_BYTES, lane);
        gpf += BLK_BYTES;
        ppf += 32;
    }

    float* sp = out + ((long long)bh * W_DIM + s0) * C_DIM + 2 * lane;
    int pb = t0;                                 // position of step at u=0

    u64 xr[16], y1r[16], y2r[32];
    #pragma unroll
    for (int j = 0; j < 16; ++j) xr[j]  = 0ull;
    #pragma unroll
    for (int j = 0; j < 16; ++j) y1r[j] = 0ull;
    #pragma unroll
    for (int j = 0; j < 32; ++j) y2r[j] = 0ull;

    unsigned cons = wsm + 2 * lane * 4;          // slot 0 base + lane offset
    const unsigned cons_hi = wsm + DEPTH * BLK_BYTES;

    for (int k = 0; k < N_IT; ++k) {
        // Need only blk k complete. Steady state with DEPTH=3: wait_group 2.
        if      (k >= N_IT - 1) asm volatile("cp.async.wait_group 0;" ::: "memory");
        else if (k == N_IT - 2) asm volatile("cp.async.wait_group 1;" ::: "memory");
        else                    asm volatile("cp.async.wait_group 2;" ::: "memory");
        __syncwarp();

        if (k == 0) {
            // y1 needed from step 17 on; y2 of steps 0..31 never read.
            #pragma unroll
            for (int u = 0; u < 32; ++u) {
                LDS_STEP(u) STAGE1(u)
            }
        } else if (k < WU_IT) {
            #pragma unroll
            for (int u = 0; u < 32; ++u) {
                LDS_STEP(u) STAGE1(u) STAGE2(u)
            }
        } else {
            #pragma unroll
            for (int u = 0; u < 32; ++u) {
                LDS_STEP(u) STAGE1(u) STAGE2(u) STAGE3_STORE(u)
            }
            sp += 32 * C_DIM;
        }

        // refill just-consumed slot with blk k+DEPTH
        if (k + DEPTH < N_IT) {
            prefetch_blk(gpf, ppf, cons - 2 * lane * 4, lane);
            gpf += BLK_BYTES;
            ppf += 32;
        }

        cons += BLK_BYTES;
        if (cons >= cons_hi) cons -= DEPTH * BLK_BYTES;
        pb += 32;
    }
}

__global__ void __launch_bounds__(32)
conv_stack_kernel(const float* __restrict__ x,
                  const float* __restrict__ w1,
                  const float* __restrict__ w2,
                  const float* __restrict__ w3,
                  float* __restrict__ out)
{
    extern __shared__ char smem[];

    const int warp = blockIdx.x;                  // 1 warp per block
    const int lane = threadIdx.x & 31;

    const unsigned wsm = (unsigned)__cvta_generic_to_shared(smem);

    const int bh  = warp >> 4;        // warp / SEGS
    const int seg = warp & 15;        // warp % SEGS

    u64 w1r[8], w2r[8], w3r[8];
    #pragma unroll
    for (int k = 0; k < 8; ++k) {
        w1r[k] = *(const u64*)(w1 + k * C_DIM + 2 * lane);
        w2r[k] = *(const u64*)(w2 + k * C_DIM + 2 * lane);
        w3r[k] = *(const u64*)(w3 + k * C_DIM + 2 * lane);
    }

    if (seg == 0 || seg == SEGS - 1) {
        run_seg<true >(x, w1r, w2r, w3r, out, bh, seg, lane, wsm);
    } else {
        run_seg<false>(x, w1r, w2r, w3r, out, bh, seg, lane, wsm);
    }
}

extern "C" void kernel_launch(void* const* d_in, const int* in_sizes, int n_in,
                              void* d_out, int out_size)
{
    const float* x  = (const float*)d_in[0];
    const float* w1 = (const float*)d_in[1];
    const float* w2 = (const float*)d_in[2];
    const float* w3 = (const float*)d_in[3];
    float* out = (float*)d_out;

    (void)in_sizes; (void)n_in; (void)out_size;

    cudaFuncSetAttribute(conv_stack_kernel,
                         cudaFuncAttributeMaxDynamicSharedMemorySize, WARP_SMEM);

    // 336 rows * 16 segs = 5376 one-warp blocks
    conv_stack_kernel<<<BH * SEGS, 32, WARP_SMEM>>>(x, w1, w2, w3, out);
}